// round 5
// baseline (speedup 1.0000x reference)
#include <cuda_runtime.h>
#include <cuda_bf16.h>

// out[i,j,:] = float(argmax(encoding_logits[clamp(qv[i,j],-128,127)+128, :]))
// (soft_codes - stop_gradient(soft_codes) == 0 exactly; gumbel_noise unused)

#define N_LEVELS 256
#define N_PIX (512 * 512)

__device__ float g_hard_table[N_LEVELS];

// Stage 1: one WARP per row (256 warps = 32 blocks x 8 warps). Lane l scans
// columns l, l+32, ..., l+224 (coalesced), then shuffle-reduce with
// first-index tiebreak (matching jnp.argmax).
__global__ void argmax_rows_kernel(const float* __restrict__ logits) {
    int warp = (blockIdx.x * blockDim.x + threadIdx.x) >> 5;   // row 0..255
    int lane = threadIdx.x & 31;
    const float* row = logits + warp * N_LEVELS;

    float best = -__FLT_MAX__;
    int bi = N_LEVELS;
#pragma unroll
    for (int j = 0; j < N_LEVELS / 32; ++j) {
        int k = lane + j * 32;
        float v = row[k];
        if (v > best || (v == best && k < bi)) { best = v; bi = k; }
    }
#pragma unroll
    for (int off = 16; off > 0; off >>= 1) {
        float ov = __shfl_down_sync(0xffffffffu, best, off);
        int oi = __shfl_down_sync(0xffffffffu, bi, off);
        if (ov > best || (ov == best && oi < bi)) { best = ov; bi = oi; }
    }
    if (lane == 0) g_hard_table[warp] = (float)bi;
}

// Stage 2: each thread handles TWO pixels (16 independent evict-first
// STG.128 per thread). Block covers 64 pixels = 256 KB contiguous.
// Layout: 8 threads per pixel; thread t -> pixels bid*64 + (t>>3) and +32.
// Every warp STG covers 4 full 128-byte lines (fully coalesced).
__global__ void __launch_bounds__(256) broadcast_kernel(
    const int* __restrict__ qv, float4* __restrict__ out) {
    int t = threadIdx.x;
    int pix0 = blockIdx.x * 64 + (t >> 3);
    int pix1 = pix0 + 32;

    int q0 = __ldg(qv + pix0);
    int q1 = __ldg(qv + pix1);
    q0 = min(max(q0, -128), 127) + 128;
    q1 = min(max(q1, -128), 127) + 128;
    float v0 = g_hard_table[q0];
    float v1 = g_hard_table[q1];
    float4 a = make_float4(v0, v0, v0, v0);
    float4 b = make_float4(v1, v1, v1, v1);

    float4* p0 = out + (long long)pix0 * 64 + (t & 7);
    float4* p1 = out + (long long)pix1 * 64 + (t & 7);
#pragma unroll
    for (int j = 0; j < 8; ++j) {
        __stcs(p0 + j * 8, a);
        __stcs(p1 + j * 8, b);
    }
}

extern "C" void kernel_launch(void* const* d_in, const int* in_sizes, int n_in,
                              void* d_out, int out_size) {
    const int* qv = (const int*)d_in[0];           // [512,512] int32
    const float* logits = (const float*)d_in[1];   // [256,256] f32
    // d_in[2] (gumbel_noise) is mathematically unused.
    float4* out = (float4*)d_out;

    argmax_rows_kernel<<<32, 256>>>(logits);       // 256 warps, 1 per row

    broadcast_kernel<<<N_PIX / 64, 256>>>(qv, out); // 4096 blocks
}